// round 4
// baseline (speedup 1.0000x reference)
#include <cuda_runtime.h>
#include <cstdint>

#define DEVINL static __device__ __forceinline__

#define N_EDGES 600000
#define N_NODES 50000
#define ETILES 4688     // ceil(600000/128)
#define NTILES 391      // ceil(50000/128)
#define GRID_E 148

// Node projection scratch (b1 folded into srcproj). Static device mem (no allocs).
static __device__ float g_srcproj[(size_t)N_NODES * 128];
static __device__ float g_dstproj[(size_t)N_NODES * 128];

// ---------------- helpers ----------------

DEVINL uint32_t smem_u32(const void* p) {
    uint32_t a;
    asm("{ .reg .u64 t; cvta.to.shared.u64 t, %1; cvt.u32.u64 %0, t; }" : "=r"(a) : "l"(p));
    return a;
}
DEVINL uint32_t tf32c(float f) {
    uint32_t r;
    asm("cvt.rna.tf32.f32 %0, %1;" : "=r"(r) : "f"(f));
    return r;
}
DEVINL uint32_t lds32(uint32_t a) {
    uint32_t v;
    asm volatile("ld.shared.b32 %0, [%1];" : "=r"(v) : "r"(a));
    return v;
}
DEVINL float2 lds64(uint32_t a) {
    float2 v;
    asm volatile("ld.shared.v2.f32 {%0,%1}, [%2];" : "=f"(v.x), "=f"(v.y) : "r"(a));
    return v;
}
DEVINL void sts64(uint32_t a, uint32_t x, uint32_t y) {
    asm volatile("st.shared.v2.b32 [%0], {%1,%2};" :: "r"(a), "r"(x), "r"(y));
}
DEVINL void sts64f(uint32_t a, float x, float y) {
    asm volatile("st.shared.v2.f32 [%0], {%1,%2};" :: "r"(a), "f"(x), "f"(y));
}
DEVINL void sts128(uint32_t a, uint32_t x, uint32_t y, uint32_t z, uint32_t w) {
    asm volatile("st.shared.v4.b32 [%0], {%1,%2,%3,%4};" :: "r"(a), "r"(x), "r"(y), "r"(z), "r"(w));
}

// XOR-swizzled [128 rows][128 cols] fp32 tile address (16B-granular swizzle).
// Conflict-free for both mma A-fragment and B-fragment scalar loads.
DEVINL uint32_t swadr(uint32_t b, int r, int c) {
    return b + (uint32_t)((r << 9) + ((c << 2) ^ ((r & 7) << 4)));
}

// m16n8k8 tf32 HMMA (base-target PTX; no arch-'a' feature needed)
DEVINL void mma8(float* d, const uint32_t* a, uint32_t b0, uint32_t b1) {
    asm volatile(
        "mma.sync.aligned.m16n8k8.row.col.f32.tf32.tf32.f32 "
        "{%0,%1,%2,%3}, {%4,%5,%6,%7}, {%8,%9}, {%0,%1,%2,%3};"
        : "+f"(d[0]), "+f"(d[1]), "+f"(d[2]), "+f"(d[3])
        : "r"(a[0]), "r"(a[1]), "r"(a[2]), "r"(a[3]), "r"(b0), "r"(b1));
}

// Load a [128 out][128 in] row-major weight into swizzled SMEM as tf32 bits.
DEVINL void load_weight(uint32_t sbW, const float* __restrict__ W, int tid) {
#pragma unroll 1
    for (int i = tid; i < 4096; i += 256) {
        int n = i >> 5, k4 = (i & 31) << 2;
        float4 v = __ldg((const float4*)W + i);
        sts128(swadr(sbW, n, k4), tf32c(v.x), tf32c(v.y), tf32c(v.z), tf32c(v.w));
    }
}

// 128x128x128 GEMM: D = A(SMEM swizzled, tf32) @ W(SMEM swizzled, tf32)^T
// 8 warps; warp w: p=w>>1 owns rows [32p,32p+32), nh=w&1 owns cols [64nh,64nh+64).
// acc[mi*32 + nt*4 + j]: m-tile mi (16 rows), n-tile nt (8 cols), mma frag j.
DEVINL void gemm_128x128(uint32_t sbA, uint32_t sbW, int p, int nh, int lq, int lm,
                         float acc[64]) {
#pragma unroll 4
    for (int ks = 0; ks < 16; ks++) {
        const int c0 = 8 * ks + lm;
        uint32_t a[2][4];
#pragma unroll
        for (int mi = 0; mi < 2; mi++) {
            const int r0 = 32 * p + 16 * mi + lq;
            a[mi][0] = lds32(swadr(sbA, r0,     c0));
            a[mi][1] = lds32(swadr(sbA, r0 + 8, c0));
            a[mi][2] = lds32(swadr(sbA, r0,     c0 + 4));
            a[mi][3] = lds32(swadr(sbA, r0 + 8, c0 + 4));
        }
#pragma unroll
        for (int nt = 0; nt < 8; nt++) {
            const int n = 64 * nh + 8 * nt + lq;
            uint32_t b0 = lds32(swadr(sbW, n, c0));
            uint32_t b1 = lds32(swadr(sbW, n, c0 + 4));
            mma8(acc + nt * 4,      a[0], b0, b1);
            mma8(acc + 32 + nt * 4, a[1], b0, b1);
        }
    }
}

// ---------------- node projection kernel ----------------
// SMEM: Ws[0,64K) Wd[64K,128K) A[128K,192K) b1[196608,+512)
#define NODE_SMEM 197120

__global__ void __launch_bounds__(256, 1)
node_kernel(const float* __restrict__ nfeat, const float* __restrict__ Ws,
            const float* __restrict__ Wd, const float* __restrict__ b1) {
    extern __shared__ char smem[];
    const uint32_t sb = smem_u32(smem);
    const uint32_t sWS = sb, sWD = sb + 65536, sAB = sb + 131072, sB1 = sb + 196608;
    const int tid = threadIdx.x, w = tid >> 5, lane = tid & 31;
    const int lq = lane >> 2, lm = lane & 3, p = w >> 1, nh = w & 1;

    load_weight(sWS, Ws, tid);
    load_weight(sWD, Wd, tid);
    if (tid < 128) ((float*)(smem + 196608))[tid] = __ldg(b1 + tid);

    const int base = blockIdx.x * 128;
    {
        const int row = tid >> 1, half = tid & 1;
        const int ng = base + row;
        const bool v = ng < N_NODES;
        const float4* s4 = (const float4*)(nfeat + (size_t)(v ? ng : 0) * 128) + half * 16;
#pragma unroll
        for (int i = 0; i < 16; i++) {
            float4 x = v ? __ldg(s4 + i) : make_float4(0.f, 0.f, 0.f, 0.f);
            sts128(swadr(sAB, row, half * 64 + i * 4),
                   tf32c(x.x), tf32c(x.y), tf32c(x.z), tf32c(x.w));
        }
    }
    __syncthreads();

    float acc[64];
#pragma unroll
    for (int i = 0; i < 64; i++) acc[i] = 0.f;
    gemm_128x128(sAB, sWS, p, nh, lq, lm, acc);
#pragma unroll
    for (int mi = 0; mi < 2; mi++)
#pragma unroll
    for (int h = 0; h < 2; h++) {
        const int R = 32 * p + 16 * mi + lq + 8 * h;
        const int ng = base + R;
        if (ng < N_NODES) {
#pragma unroll
            for (int nt = 0; nt < 8; nt++) {
                const int cb = 64 * nh + 8 * nt + 2 * lm;
                float2 bb = lds64(sB1 + cb * 4);
                float2 o;
                o.x = acc[mi * 32 + nt * 4 + 2 * h]     + bb.x;
                o.y = acc[mi * 32 + nt * 4 + 2 * h + 1] + bb.y;
                *(float2*)(g_srcproj + (size_t)ng * 128 + cb) = o;
            }
        }
    }

#pragma unroll
    for (int i = 0; i < 64; i++) acc[i] = 0.f;
    gemm_128x128(sAB, sWD, p, nh, lq, lm, acc);
#pragma unroll
    for (int mi = 0; mi < 2; mi++)
#pragma unroll
    for (int h = 0; h < 2; h++) {
        const int R = 32 * p + 16 * mi + lq + 8 * h;
        const int ng = base + R;
        if (ng < N_NODES) {
#pragma unroll
            for (int nt = 0; nt < 8; nt++) {
                const int cb = 64 * nh + 8 * nt + 2 * lm;
                float2 o;
                o.x = acc[mi * 32 + nt * 4 + 2 * h];
                o.y = acc[mi * 32 + nt * 4 + 2 * h + 1];
                *(float2*)(g_dstproj + (size_t)ng * 128 + cb) = o;
            }
        }
    }
}

// ---------------- fused edge kernel (persistent) ----------------
// SMEM: We[0,64K) Wo[64K,128K) A[128K,192K) LN[196608,+2048)
//       bo@198656 gamma@199168 beta@199680
#define EDGE_SMEM 200192

__global__ void __launch_bounds__(256, 1)
edge_kernel(const float* __restrict__ efeat, const int* __restrict__ src,
            const int* __restrict__ dst, const float* __restrict__ We,
            const float* __restrict__ Wo, const float* __restrict__ bo,
            const float* __restrict__ gamma, const float* __restrict__ beta,
            float* __restrict__ out) {
    extern __shared__ char smem[];
    const uint32_t sb = smem_u32(smem);
    const uint32_t sWE = sb, sWO = sb + 65536, sAB = sb + 131072;
    const uint32_t sLN = sb + 196608, sBO = sb + 198656, sGA = sb + 199168, sBE = sb + 199680;
    const int tid = threadIdx.x, w = tid >> 5, lane = tid & 31;
    const int lq = lane >> 2, lm = lane & 3, p = w >> 1, nh = w & 1;

    load_weight(sWE, We, tid);
    load_weight(sWO, Wo, tid);
    if (tid < 128) {
        ((float*)(smem + 198656))[tid] = __ldg(bo + tid);
        ((float*)(smem + 199168))[tid] = __ldg(gamma + tid);
        ((float*)(smem + 199680))[tid] = __ldg(beta + tid);
    }

    for (int tile = blockIdx.x; tile < ETILES; tile += GRID_E) {
        const int base = tile * 128;
        __syncthreads();                      // (a) A-buffer free from prev tile
        {   // efeat tile -> swizzled SMEM (tf32 bits)
            const int row = tid >> 1, half = tid & 1;
            const int e = base + row;
            const bool v = e < N_EDGES;
            const float4* s4 = (const float4*)(efeat + (size_t)(v ? e : 0) * 128) + half * 16;
#pragma unroll
            for (int i = 0; i < 16; i++) {
                float4 x = v ? __ldg(s4 + i) : make_float4(0.f, 0.f, 0.f, 0.f);
                sts128(swadr(sAB, row, half * 64 + i * 4),
                       tf32c(x.x), tf32c(x.y), tf32c(x.z), tf32c(x.w));
            }
        }
        __syncthreads();                      // (b)

        float acc[64];
#pragma unroll
        for (int i = 0; i < 64; i++) acc[i] = 0.f;
        gemm_128x128(sAB, sWE, p, nh, lq, lm, acc);   // h-pre = efeat @ We^T
        __syncthreads();                      // (c) all warps done reading A

        // epilogue1: + srcproj[src] (b1 folded) + dstproj[dst], SiLU, act -> A-buffer
#pragma unroll
        for (int mi = 0; mi < 2; mi++)
#pragma unroll
        for (int h = 0; h < 2; h++) {
            const int R = 32 * p + 16 * mi + lq + 8 * h;
            const int e = base + R;
            const bool v = e < N_EDGES;
            const int si = v ? __ldg(src + e) : 0;
            const int di = v ? __ldg(dst + e) : 0;
            const float2* ps = (const float2*)(g_srcproj + (size_t)si * 128);
            const float2* pd = (const float2*)(g_dstproj + (size_t)di * 128);
#pragma unroll
            for (int nt = 0; nt < 8; nt++) {
                const int c2 = 32 * nh + 4 * nt + lm;   // float2 column index
                float2 a = __ldg(ps + c2), b2 = __ldg(pd + c2);
                float x0 = acc[mi * 32 + nt * 4 + 2 * h]     + a.x + b2.x;
                float x1 = acc[mi * 32 + nt * 4 + 2 * h + 1] + a.y + b2.y;
                x0 = __fdividef(x0, 1.f + __expf(-x0));
                x1 = __fdividef(x1, 1.f + __expf(-x1));
                sts64(swadr(sAB, R, 64 * nh + 8 * nt + 2 * lm), tf32c(x0), tf32c(x1));
            }
        }
        __syncthreads();                      // (d) act tile complete

#pragma unroll
        for (int i = 0; i < 64; i++) acc[i] = 0.f;
        gemm_128x128(sAB, sWO, p, nh, lq, lm, acc);   // o-pre = act @ Wo^T

        // epilogue2a: + bo, LayerNorm partials (quad shfl + cross-warp SMEM)
#pragma unroll
        for (int mi = 0; mi < 2; mi++)
#pragma unroll
        for (int h = 0; h < 2; h++) {
            float s = 0.f, q = 0.f;
#pragma unroll
            for (int nt = 0; nt < 8; nt++) {
                float2 bb = lds64(sBO + (64 * nh + 8 * nt + 2 * lm) * 4);
                float x0 = acc[mi * 32 + nt * 4 + 2 * h]     + bb.x;
                float x1 = acc[mi * 32 + nt * 4 + 2 * h + 1] + bb.y;
                acc[mi * 32 + nt * 4 + 2 * h]     = x0;
                acc[mi * 32 + nt * 4 + 2 * h + 1] = x1;
                s += x0 + x1;
                q += x0 * x0 + x1 * x1;
            }
            s += __shfl_xor_sync(0xffffffffu, s, 1);
            q += __shfl_xor_sync(0xffffffffu, q, 1);
            s += __shfl_xor_sync(0xffffffffu, s, 2);
            q += __shfl_xor_sync(0xffffffffu, q, 2);
            if (lm == 0) {
                const int R = 32 * p + 16 * mi + lq + 8 * h;
                sts64f(sLN + (uint32_t)(nh * 128 + R) * 8, s, q);
            }
        }
        __syncthreads();                      // (e) LN partials visible

        // epilogue2b: normalize, affine, + residual efeat (L2-hot), store
#pragma unroll
        for (int mi = 0; mi < 2; mi++)
#pragma unroll
        for (int h = 0; h < 2; h++) {
            const int R = 32 * p + 16 * mi + lq + 8 * h;
            const int e = base + R;
            const bool v = e < N_EDGES;
            float2 p0 = lds64(sLN + (uint32_t)R * 8);
            float2 p1 = lds64(sLN + (uint32_t)(128 + R) * 8);
            const float mu  = (p0.x + p1.x) * 0.0078125f;
            const float var = (p0.y + p1.y) * 0.0078125f - mu * mu;
            const float rs  = rsqrtf(var + 1e-5f);
            const float2* pe = (const float2*)(efeat + (size_t)(v ? e : 0) * 128);
            float2* po = (float2*)(out + (size_t)e * 128);
#pragma unroll
            for (int nt = 0; nt < 8; nt++) {
                const int c2 = 32 * nh + 4 * nt + lm;
                float2 g  = lds64(sGA + (uint32_t)c2 * 8);
                float2 bt = lds64(sBE + (uint32_t)c2 * 8);
                float2 r = v ? __ldg(pe + c2) : make_float2(0.f, 0.f);
                float2 o;
                o.x = (acc[mi * 32 + nt * 4 + 2 * h]     - mu) * rs * g.x + bt.x + r.x;
                o.y = (acc[mi * 32 + nt * 4 + 2 * h + 1] - mu) * rs * g.y + bt.y + r.y;
                if (v) po[c2] = o;
            }
        }
    }
}

// ---------------- launch ----------------

extern "C" void kernel_launch(void* const* d_in, const int* in_sizes, int n_in,
                              void* d_out, int out_size) {
    const float* efeat = (const float*)d_in[0];
    const float* nfeat = (const float*)d_in[1];
    const int*   src   = (const int*)d_in[2];
    const int*   dst   = (const int*)d_in[3];
    const float* We    = (const float*)d_in[4];
    const float* Ws    = (const float*)d_in[5];
    const float* Wd    = (const float*)d_in[6];
    const float* b1    = (const float*)d_in[7];
    const float* Wo    = (const float*)d_in[8];
    const float* bo    = (const float*)d_in[9];
    const float* gamma = (const float*)d_in[10];
    const float* beta  = (const float*)d_in[11];
    float* out = (float*)d_out;

    cudaFuncSetAttribute(node_kernel, cudaFuncAttributeMaxDynamicSharedMemorySize, NODE_SMEM);
    cudaFuncSetAttribute(edge_kernel, cudaFuncAttributeMaxDynamicSharedMemorySize, EDGE_SMEM);

    // second output: nfeat passthrough
    cudaMemcpyAsync(out + (size_t)N_EDGES * 128, nfeat,
                    (size_t)N_NODES * 128 * sizeof(float), cudaMemcpyDeviceToDevice);

    node_kernel<<<NTILES, 256, NODE_SMEM>>>(nfeat, Ws, Wd, b1);
    edge_kernel<<<GRID_E, 256, EDGE_SMEM>>>(efeat, src, dst, We, Wo, bo, gamma, beta, out);
}

// round 5
// speedup vs baseline: 1.1414x; 1.1414x over previous
#include <cuda_runtime.h>
#include <cstdint>

#define DEVINL static __device__ __forceinline__

#define N_EDGES 600000
#define N_NODES 50000
#define ETILES 4688     // ceil(600000/128)
#define NTILES 391      // ceil(50000/128)
#define GRID_E 148

// Node projection scratch (b1 folded into srcproj). Static device mem (no allocs).
static __device__ float g_srcproj[(size_t)N_NODES * 128];
static __device__ float g_dstproj[(size_t)N_NODES * 128];

// ---------------- helpers ----------------

DEVINL uint32_t smem_u32(const void* p) {
    uint32_t a;
    asm("{ .reg .u64 t; cvta.to.shared.u64 t, %1; cvt.u32.u64 %0, t; }" : "=r"(a) : "l"(p));
    return a;
}
DEVINL uint32_t tf32c(float f) {
    uint32_t r;
    asm("cvt.rna.tf32.f32 %0, %1;" : "=r"(r) : "f"(f));
    return r;
}
DEVINL uint32_t lds32(uint32_t a) {
    uint32_t v;
    asm volatile("ld.shared.b32 %0, [%1];" : "=r"(v) : "r"(a));
    return v;
}
DEVINL float2 lds64(uint32_t a) {
    float2 v;
    asm volatile("ld.shared.v2.f32 {%0,%1}, [%2];" : "=f"(v.x), "=f"(v.y) : "r"(a));
    return v;
}
DEVINL void sts64(uint32_t a, uint32_t x, uint32_t y) {
    asm volatile("st.shared.v2.b32 [%0], {%1,%2};" :: "r"(a), "r"(x), "r"(y));
}
DEVINL void sts64f(uint32_t a, float x, float y) {
    asm volatile("st.shared.v2.f32 [%0], {%1,%2};" :: "r"(a), "f"(x), "f"(y));
}
DEVINL void sts128(uint32_t a, uint32_t x, uint32_t y, uint32_t z, uint32_t w) {
    asm volatile("st.shared.v4.b32 [%0], {%1,%2,%3,%4};" :: "r"(a), "r"(x), "r"(y), "r"(z), "r"(w));
}
DEVINL void cpasync16(uint32_t s, const void* g, int srcbytes) {
    asm volatile("cp.async.cg.shared.global [%0], [%1], 16, %2;"
                 :: "r"(s), "l"(g), "r"(srcbytes));
}
DEVINL void cpcommit() { asm volatile("cp.async.commit_group;" ::: "memory"); }
DEVINL void cpwait0()  { asm volatile("cp.async.wait_group 0;" ::: "memory"); }

// silu(x) = x*sigmoid(x) = h + h*tanh(h), h = x/2  (1 MUFU)
DEVINL float silu_f(float x) {
    float h = 0.5f * x, t;
    asm("tanh.approx.f32 %0, %1;" : "=f"(t) : "f"(h));
    return fmaf(h, t, h);
}

// XOR-swizzled [128 rows][128 cols] fp32 tile address (16B-granular swizzle).
DEVINL uint32_t swadr(uint32_t b, int r, int c) {
    return b + (uint32_t)((r << 9) + ((c << 2) ^ ((r & 7) << 4)));
}

// m16n8k8 tf32 HMMA (base-target PTX)
DEVINL void mma8(float* d, const uint32_t* a, uint32_t b0, uint32_t b1) {
    asm volatile(
        "mma.sync.aligned.m16n8k8.row.col.f32.tf32.tf32.f32 "
        "{%0,%1,%2,%3}, {%4,%5,%6,%7}, {%8,%9}, {%0,%1,%2,%3};"
        : "+f"(d[0]), "+f"(d[1]), "+f"(d[2]), "+f"(d[3])
        : "r"(a[0]), "r"(a[1]), "r"(a[2]), "r"(a[3]), "r"(b0), "r"(b1));
}

// Load [128 out][128 in] row-major weight into swizzled SMEM as tf32 bits (512 thr).
DEVINL void load_weight(uint32_t sbW, const float* __restrict__ W, int tid) {
#pragma unroll 1
    for (int i = tid; i < 4096; i += 512) {
        int n = i >> 5, k4 = (i & 31) << 2;
        float4 v = __ldg((const float4*)W + i);
        sts128(swadr(sbW, n, k4), tf32c(v.x), tf32c(v.y), tf32c(v.z), tf32c(v.w));
    }
}

// 128x128x128 GEMM, 16 warps. Warp w: rg=w>>2 rows [32rg,+32), cg=w&3 cols [32cg,+32).
// acc[(mi*4+nt)*4 + j]: 32 floats per thread.
DEVINL void gemm512(uint32_t sbA, uint32_t sbW, int rg, int cg, int lq, int lm,
                    float acc[32]) {
#pragma unroll 2
    for (int ks = 0; ks < 16; ks++) {
        const int c0 = 8 * ks + lm;
        uint32_t a[2][4];
#pragma unroll
        for (int mi = 0; mi < 2; mi++) {
            const int r0 = 32 * rg + 16 * mi + lq;
            a[mi][0] = lds32(swadr(sbA, r0,     c0));
            a[mi][1] = lds32(swadr(sbA, r0 + 8, c0));
            a[mi][2] = lds32(swadr(sbA, r0,     c0 + 4));
            a[mi][3] = lds32(swadr(sbA, r0 + 8, c0 + 4));
        }
#pragma unroll
        for (int nt = 0; nt < 4; nt++) {
            const int n = 32 * cg + 8 * nt + lq;
            uint32_t b0 = lds32(swadr(sbW, n, c0));
            uint32_t b1 = lds32(swadr(sbW, n, c0 + 4));
            mma8(acc + nt * 4,      a[0], b0, b1);
            mma8(acc + 16 + nt * 4, a[1], b0, b1);
        }
    }
}

// ---------------- node projection kernel ----------------
// SMEM: Ws[0,64K) Wd[64K,128K) A[128K,192K) b1[196608,+512)
#define NODE_SMEM 197120

__global__ void __launch_bounds__(512, 1)
node_kernel(const float* __restrict__ nfeat, const float* __restrict__ Ws,
            const float* __restrict__ Wd, const float* __restrict__ b1) {
    extern __shared__ char smem[];
    const uint32_t sb = smem_u32(smem);
    const uint32_t sWS = sb, sWD = sb + 65536, sAB = sb + 131072, sB1 = sb + 196608;
    const int tid = threadIdx.x, w = tid >> 5, lane = tid & 31;
    const int lq = lane >> 2, lm = lane & 3, rg = w >> 2, cg = w & 3;

    load_weight(sWS, Ws, tid);
    load_weight(sWD, Wd, tid);
    if (tid < 128) ((float*)(smem + 196608))[tid] = __ldg(b1 + tid);

    const int base = blockIdx.x * 128;
#pragma unroll
    for (int i = 0; i < 8; i++) {
        const int f4 = tid + 512 * i;
        const int row = f4 >> 5, c4 = f4 & 31;
        const int ng = base + row;
        const bool v = ng < N_NODES;
        float4 x = v ? __ldg((const float4*)(nfeat + (size_t)ng * 128) + c4)
                     : make_float4(0.f, 0.f, 0.f, 0.f);
        sts128(swadr(sAB, row, c4 * 4), tf32c(x.x), tf32c(x.y), tf32c(x.z), tf32c(x.w));
    }
    __syncthreads();

    float acc[32];
#pragma unroll
    for (int i = 0; i < 32; i++) acc[i] = 0.f;
    gemm512(sAB, sWS, rg, cg, lq, lm, acc);
#pragma unroll
    for (int mi = 0; mi < 2; mi++)
#pragma unroll
    for (int h = 0; h < 2; h++) {
        const int R = 32 * rg + 16 * mi + 8 * h + lq;
        const int ng = base + R;
        if (ng < N_NODES) {
#pragma unroll
            for (int nt = 0; nt < 4; nt++) {
                const int col = 32 * cg + 8 * nt + 2 * lm;
                float2 bb = lds64(sB1 + col * 4);
                float2 o;
                o.x = acc[(mi * 4 + nt) * 4 + 2 * h]     + bb.x;
                o.y = acc[(mi * 4 + nt) * 4 + 2 * h + 1] + bb.y;
                *(float2*)(g_srcproj + (size_t)ng * 128 + col) = o;
            }
        }
    }

#pragma unroll
    for (int i = 0; i < 32; i++) acc[i] = 0.f;
    gemm512(sAB, sWD, rg, cg, lq, lm, acc);
#pragma unroll
    for (int mi = 0; mi < 2; mi++)
#pragma unroll
    for (int h = 0; h < 2; h++) {
        const int R = 32 * rg + 16 * mi + 8 * h + lq;
        const int ng = base + R;
        if (ng < N_NODES) {
#pragma unroll
            for (int nt = 0; nt < 4; nt++) {
                const int col = 32 * cg + 8 * nt + 2 * lm;
                float2 o;
                o.x = acc[(mi * 4 + nt) * 4 + 2 * h];
                o.y = acc[(mi * 4 + nt) * 4 + 2 * h + 1];
                *(float2*)(g_dstproj + (size_t)ng * 128 + col) = o;
            }
        }
    }
}

// ---------------- fused edge kernel (persistent, 512 thr) ----------------
// SMEM: We[0,64K) Wo[64K,128K) A[128K,192K) LN[196608,+4K)
//       bo@200704 gamma@201216 beta@201728
#define EDGE_SMEM 202240

// Prefetch one 128x128 fp32 tile of efeat into swizzled SMEM via cp.async.
DEVINL void prefetch_efeat(uint32_t sAB, const float* __restrict__ efeat,
                           int tile, int tid) {
    const int base = tile * 128;
#pragma unroll
    for (int i = 0; i < 8; i++) {
        const int f4 = tid + 512 * i;
        const int row = f4 >> 5, c4 = f4 & 31;
        const int e = base + row;
        const bool v = e < N_EDGES;
        const float* g = efeat + (size_t)(v ? e : 0) * 128 + c4 * 4;
        cpasync16(swadr(sAB, row, c4 * 4), g, v ? 16 : 0);
    }
    cpcommit();
}

__global__ void __launch_bounds__(512, 1)
edge_kernel(const float* __restrict__ efeat, const int* __restrict__ src,
            const int* __restrict__ dst, const float* __restrict__ We,
            const float* __restrict__ Wo, const float* __restrict__ bo,
            const float* __restrict__ gamma, const float* __restrict__ beta,
            float* __restrict__ out) {
    extern __shared__ char smem[];
    const uint32_t sb = smem_u32(smem);
    const uint32_t sWE = sb, sWO = sb + 65536, sAB = sb + 131072;
    const uint32_t sLN = sb + 196608, sBO = sb + 200704, sGA = sb + 201216, sBE = sb + 201728;
    const int tid = threadIdx.x, w = tid >> 5, lane = tid & 31;
    const int lq = lane >> 2, lm = lane & 3, rg = w >> 2, cg = w & 3;

    load_weight(sWE, We, tid);
    load_weight(sWO, Wo, tid);
    if (tid < 128) {
        ((float*)(smem + 200704))[tid] = __ldg(bo + tid);
        ((float*)(smem + 201216))[tid] = __ldg(gamma + tid);
        ((float*)(smem + 201728))[tid] = __ldg(beta + tid);
    }
    // prologue: prefetch first tile (raw fp32; tf32 mma truncates low bits)
    prefetch_efeat(sAB, efeat, blockIdx.x, tid);

    for (int tile = blockIdx.x; tile < ETILES; tile += GRID_E) {
        const int base = tile * 128;
        cpwait0();
        __syncthreads();                      // (a) efeat tile ready in A

        // prefetch gather indices early (consumed after GEMM1)
        int si[4], di[4];
        bool vr[4];
#pragma unroll
        for (int mi = 0; mi < 2; mi++)
#pragma unroll
        for (int h = 0; h < 2; h++) {
            const int R = 32 * rg + 16 * mi + 8 * h + lq;
            const int e = base + R;
            const bool v = e < N_EDGES;
            vr[mi * 2 + h] = v;
            si[mi * 2 + h] = v ? __ldg(src + e) : 0;
            di[mi * 2 + h] = v ? __ldg(dst + e) : 0;
        }

        float acc[32];
#pragma unroll
        for (int i = 0; i < 32; i++) acc[i] = 0.f;
        gemm512(sAB, sWE, rg, cg, lq, lm, acc);   // h-pre = efeat @ We^T
        __syncthreads();                      // (c) all warps done reading A

        // epilogue1: + srcproj[src] (b1 folded) + dstproj[dst], SiLU, act -> A
#pragma unroll
        for (int mi = 0; mi < 2; mi++)
#pragma unroll
        for (int h = 0; h < 2; h++) {
            const int R = 32 * rg + 16 * mi + 8 * h + lq;
            const float2* ps = (const float2*)(g_srcproj + (size_t)si[mi * 2 + h] * 128);
            const float2* pd = (const float2*)(g_dstproj + (size_t)di[mi * 2 + h] * 128);
#pragma unroll
            for (int nt = 0; nt < 4; nt++) {
                const int c2 = 16 * cg + 4 * nt + lm;   // float2 column index
                float2 a = __ldg(ps + c2), b2 = __ldg(pd + c2);
                float x0 = acc[(mi * 4 + nt) * 4 + 2 * h]     + a.x + b2.x;
                float x1 = acc[(mi * 4 + nt) * 4 + 2 * h + 1] + a.y + b2.y;
                x0 = silu_f(x0);
                x1 = silu_f(x1);
                sts64(swadr(sAB, R, 32 * cg + 8 * nt + 2 * lm), tf32c(x0), tf32c(x1));
            }
        }
        __syncthreads();                      // (d) act tile complete

#pragma unroll
        for (int i = 0; i < 32; i++) acc[i] = 0.f;
        gemm512(sAB, sWO, rg, cg, lq, lm, acc);   // o-pre = act @ Wo^T

        // epilogue2a: + bo, LayerNorm partials (quad shfl + cross-warp SMEM)
#pragma unroll
        for (int mi = 0; mi < 2; mi++)
#pragma unroll
        for (int h = 0; h < 2; h++) {
            float s = 0.f, q = 0.f;
#pragma unroll
            for (int nt = 0; nt < 4; nt++) {
                float2 bb = lds64(sBO + (32 * cg + 8 * nt + 2 * lm) * 4);
                float x0 = acc[(mi * 4 + nt) * 4 + 2 * h]     + bb.x;
                float x1 = acc[(mi * 4 + nt) * 4 + 2 * h + 1] + bb.y;
                acc[(mi * 4 + nt) * 4 + 2 * h]     = x0;
                acc[(mi * 4 + nt) * 4 + 2 * h + 1] = x1;
                s += x0 + x1;
                q += x0 * x0 + x1 * x1;
            }
            s += __shfl_xor_sync(0xffffffffu, s, 1);
            q += __shfl_xor_sync(0xffffffffu, q, 1);
            s += __shfl_xor_sync(0xffffffffu, s, 2);
            q += __shfl_xor_sync(0xffffffffu, q, 2);
            if (lm == 0) {
                const int R = 32 * rg + 16 * mi + 8 * h + lq;
                sts64f(sLN + (uint32_t)(cg * 128 + R) * 8, s, q);
            }
        }
        __syncthreads();                      // (e) LN partials visible; A free

        // prefetch next tile's efeat into A (overlaps epilogue2b)
        if (tile + GRID_E < ETILES)
            prefetch_efeat(sAB, efeat, tile + GRID_E, tid);

        // epilogue2b: normalize, affine, + residual efeat (L2-hot), store
#pragma unroll
        for (int mi = 0; mi < 2; mi++)
#pragma unroll
        for (int h = 0; h < 2; h++) {
            const int R = 32 * rg + 16 * mi + 8 * h + lq;
            const int e = base + R;
            const bool v = vr[mi * 2 + h];
            float2 p0 = lds64(sLN + (uint32_t)(R) * 8);
            float2 p1 = lds64(sLN + (uint32_t)(128 + R) * 8);
            float2 p2 = lds64(sLN + (uint32_t)(256 + R) * 8);
            float2 p3 = lds64(sLN + (uint32_t)(384 + R) * 8);
            const float mu  = (p0.x + p1.x + p2.x + p3.x) * 0.0078125f;
            const float var = (p0.y + p1.y + p2.y + p3.y) * 0.0078125f - mu * mu;
            const float rs  = rsqrtf(var + 1e-5f);
            const float2* pe = (const float2*)(efeat + (size_t)(v ? e : 0) * 128);
            float2* po = (float2*)(out + (size_t)e * 128);
#pragma unroll
            for (int nt = 0; nt < 4; nt++) {
                const int c2 = 16 * cg + 4 * nt + lm;
                float2 g  = lds64(sGA + (uint32_t)c2 * 8);
                float2 bt = lds64(sBE + (uint32_t)c2 * 8);
                float2 r = v ? __ldg(pe + c2) : make_float2(0.f, 0.f);
                float2 o;
                o.x = (acc[(mi * 4 + nt) * 4 + 2 * h]     - mu) * rs * g.x + bt.x + r.x;
                o.y = (acc[(mi * 4 + nt) * 4 + 2 * h + 1] - mu) * rs * g.y + bt.y + r.y;
                if (v) po[c2] = o;
            }
        }
    }
}

// ---------------- launch ----------------

extern "C" void kernel_launch(void* const* d_in, const int* in_sizes, int n_in,
                              void* d_out, int out_size) {
    const float* efeat = (const float*)d_in[0];
    const float* nfeat = (const float*)d_in[1];
    const int*   src   = (const int*)d_in[2];
    const int*   dst   = (const int*)d_in[3];
    const float* We    = (const float*)d_in[4];
    const float* Ws    = (const float*)d_in[5];
    const float* Wd    = (const float*)d_in[6];
    const float* b1    = (const float*)d_in[7];
    const float* Wo    = (const float*)d_in[8];
    const float* bo    = (const float*)d_in[9];
    const float* gamma = (const float*)d_in[10];
    const float* beta  = (const float*)d_in[11];
    float* out = (float*)d_out;

    cudaFuncSetAttribute(node_kernel, cudaFuncAttributeMaxDynamicSharedMemorySize, NODE_SMEM);
    cudaFuncSetAttribute(edge_kernel, cudaFuncAttributeMaxDynamicSharedMemorySize, EDGE_SMEM);

    // second output: nfeat passthrough
    cudaMemcpyAsync(out + (size_t)N_EDGES * 128, nfeat,
                    (size_t)N_NODES * 128 * sizeof(float), cudaMemcpyDeviceToDevice);

    node_kernel<<<NTILES, 512, NODE_SMEM>>>(nfeat, Ws, Wd, b1);
    edge_kernel<<<GRID_E, 512, EDGE_SMEM>>>(efeat, src, dst, We, Wo, bo, gamma, beta, out);
}

// round 6
// speedup vs baseline: 1.3332x; 1.1681x over previous
#include <cuda_runtime.h>
#include <cstdint>

#define DEVINL static __device__ __forceinline__

#define N_EDGES 600000
#define N_NODES 50000
#define ETILES 4688     // ceil(600000/128)
#define NTILES 391      // ceil(50000/128)
#define GRID_E 148

// Node projection scratch (b1 folded into srcproj). Static device mem (no allocs).
static __device__ float g_srcproj[(size_t)N_NODES * 128];
static __device__ float g_dstproj[(size_t)N_NODES * 128];

// ---------------- helpers ----------------

DEVINL uint32_t smem_u32(const void* p) {
    uint32_t a;
    asm("{ .reg .u64 t; cvta.to.shared.u64 t, %1; cvt.u32.u64 %0, t; }" : "=r"(a) : "l"(p));
    return a;
}
DEVINL uint32_t tf32c(float f) {
    uint32_t r;
    asm("cvt.rna.tf32.f32 %0, %1;" : "=r"(r) : "f"(f));
    return r;
}
DEVINL uint32_t lds32(uint32_t a) {
    uint32_t v;
    asm volatile("ld.shared.b32 %0, [%1];" : "=r"(v) : "r"(a));
    return v;
}
DEVINL float4 lds128f(uint32_t a) {
    float4 v;
    asm volatile("ld.shared.v4.f32 {%0,%1,%2,%3}, [%4];"
                 : "=f"(v.x), "=f"(v.y), "=f"(v.z), "=f"(v.w) : "r"(a));
    return v;
}
DEVINL void sts64f(uint32_t a, float x, float y) {
    asm volatile("st.shared.v2.f32 [%0], {%1,%2};" :: "r"(a), "f"(x), "f"(y));
}
DEVINL void sts128(uint32_t a, uint32_t x, uint32_t y, uint32_t z, uint32_t w) {
    asm volatile("st.shared.v4.b32 [%0], {%1,%2,%3,%4};" :: "r"(a), "r"(x), "r"(y), "r"(z), "r"(w));
}
DEVINL void cpasync16(uint32_t s, const void* g, int srcbytes) {
    asm volatile("cp.async.cg.shared.global [%0], [%1], 16, %2;"
                 :: "r"(s), "l"(g), "r"(srcbytes));
}
DEVINL void cpcommit() { asm volatile("cp.async.commit_group;" ::: "memory"); }
DEVINL void cpwait0()  { asm volatile("cp.async.wait_group 0;" ::: "memory"); }

// silu(x) = x*sigmoid(x) = h + h*tanh(h), h = x/2  (1 MUFU)
DEVINL float silu_f(float x) {
    float h = 0.5f * x, t;
    asm("tanh.approx.f32 %0, %1;" : "=f"(t) : "f"(h));
    return fmaf(h, t, h);
}

// Out-dim permutation: n = 32c+8a+2b+e -> 32c+8b+2a+e  (swap 2-bit fields a,b).
// Applied to weight SMEM rows so that a thread's D-fragment columns are the
// CONTIGUOUS logical columns 32*cg + 8*lm + {0..7}.
DEVINL int permn(int n) {
    return (n & 0x61) | ((n & 6) << 2) | ((n >> 2) & 6);
}

// XOR-swizzled [128 rows][128 cols] fp32 tile address (16B-granular swizzle).
DEVINL uint32_t swadr(uint32_t b, int r, int c) {
    return b + (uint32_t)((r << 9) + ((c << 2) ^ ((r & 7) << 4)));
}

// m16n8k8 tf32 HMMA (base-target PTX)
DEVINL void mma8(float* d, const uint32_t* a, uint32_t b0, uint32_t b1) {
    asm volatile(
        "mma.sync.aligned.m16n8k8.row.col.f32.tf32.tf32.f32 "
        "{%0,%1,%2,%3}, {%4,%5,%6,%7}, {%8,%9}, {%0,%1,%2,%3};"
        : "+f"(d[0]), "+f"(d[1]), "+f"(d[2]), "+f"(d[3])
        : "r"(a[0]), "r"(a[1]), "r"(a[2]), "r"(a[3]), "r"(b0), "r"(b1));
}

// Load [128 out][128 in] row-major weight into swizzled SMEM (out-rows permuted).
DEVINL void load_weight(uint32_t sbW, const float* __restrict__ W, int tid) {
#pragma unroll 1
    for (int i = tid; i < 4096; i += 512) {
        int n = i >> 5, k4 = (i & 31) << 2;
        float4 v = __ldg((const float4*)W + i);
        sts128(swadr(sbW, permn(n), k4), tf32c(v.x), tf32c(v.y), tf32c(v.z), tf32c(v.w));
    }
}

// 128x128x128 GEMM, 16 warps. Warp w: rg=w>>2 rows [32rg,+32), cg=w&3 cols [32cg,+32).
// acc[(mi*4+nt)*4 + 2*h + e]; logical col of (nt,e) = 32cg + 8lm + 2nt + e.
DEVINL void gemm512(uint32_t sbA, uint32_t sbW, int rg, int cg, int lq, int lm,
                    float acc[32]) {
#pragma unroll 2
    for (int ks = 0; ks < 16; ks++) {
        const int c0 = 8 * ks + lm;
        uint32_t a[2][4];
#pragma unroll
        for (int mi = 0; mi < 2; mi++) {
            const int r0 = 32 * rg + 16 * mi + lq;
            a[mi][0] = lds32(swadr(sbA, r0,     c0));
            a[mi][1] = lds32(swadr(sbA, r0 + 8, c0));
            a[mi][2] = lds32(swadr(sbA, r0,     c0 + 4));
            a[mi][3] = lds32(swadr(sbA, r0 + 8, c0 + 4));
        }
#pragma unroll
        for (int nt = 0; nt < 4; nt++) {
            const int n = 32 * cg + 8 * nt + lq;
            uint32_t b0 = lds32(swadr(sbW, n, c0));
            uint32_t b1 = lds32(swadr(sbW, n, c0 + 4));
            mma8(acc + nt * 4,      a[0], b0, b1);
            mma8(acc + 16 + nt * 4, a[1], b0, b1);
        }
    }
}

// Extract thread's 8 contiguous logical cols (j = 2*nt+e) for row-rep (mi,h).
#define ACCJ(mi, h, j) acc[((mi) * 4 + ((j) >> 1)) * 4 + 2 * (h) + ((j) & 1)]

// ---------------- node projection kernel ----------------
// SMEM: Ws[0,64K) Wd[64K,128K) A[128K,192K) b1[196608,+512)
#define NODE_SMEM 197120

__global__ void __launch_bounds__(512, 1)
node_kernel(const float* __restrict__ nfeat, const float* __restrict__ Ws,
            const float* __restrict__ Wd, const float* __restrict__ b1,
            float* __restrict__ nfeat_out) {
    extern __shared__ char smem[];
    const uint32_t sb = smem_u32(smem);
    const uint32_t sWS = sb, sWD = sb + 65536, sAB = sb + 131072, sB1 = sb + 196608;
    const int tid = threadIdx.x, w = tid >> 5, lane = tid & 31;
    const int lq = lane >> 2, lm = lane & 3, rg = w >> 2, cg = w & 3;

    load_weight(sWS, Ws, tid);
    load_weight(sWD, Wd, tid);
    if (tid < 128) ((float*)(smem + 196608))[tid] = __ldg(b1 + tid);

    const int base = blockIdx.x * 128;
#pragma unroll
    for (int i = 0; i < 8; i++) {
        const int f4 = tid + 512 * i;
        const int row = f4 >> 5, c4 = f4 & 31;
        const int ng = base + row;
        const bool v = ng < N_NODES;
        float4 x = v ? __ldg((const float4*)(nfeat + (size_t)ng * 128) + c4)
                     : make_float4(0.f, 0.f, 0.f, 0.f);
        // fused nfeat passthrough (exact fp32 copy)
        if (v) *((float4*)(nfeat_out + (size_t)ng * 128) + c4) = x;
        sts128(swadr(sAB, row, c4 * 4), tf32c(x.x), tf32c(x.y), tf32c(x.z), tf32c(x.w));
    }
    __syncthreads();

    const int Lb = 32 * cg + 8 * lm;                 // thread's logical col base
    const float4 bb0 = lds128f(sB1 + (uint32_t)Lb * 4);
    const float4 bb1 = lds128f(sB1 + (uint32_t)Lb * 4 + 16);

    float acc[32];
#pragma unroll
    for (int i = 0; i < 32; i++) acc[i] = 0.f;
    gemm512(sAB, sWS, rg, cg, lq, lm, acc);
#pragma unroll
    for (int mi = 0; mi < 2; mi++)
#pragma unroll
    for (int h = 0; h < 2; h++) {
        const int ng = base + 32 * rg + 16 * mi + 8 * h + lq;
        if (ng < N_NODES) {
            float4 o0, o1;
            o0.x = ACCJ(mi, h, 0) + bb0.x;  o0.y = ACCJ(mi, h, 1) + bb0.y;
            o0.z = ACCJ(mi, h, 2) + bb0.z;  o0.w = ACCJ(mi, h, 3) + bb0.w;
            o1.x = ACCJ(mi, h, 4) + bb1.x;  o1.y = ACCJ(mi, h, 5) + bb1.y;
            o1.z = ACCJ(mi, h, 6) + bb1.z;  o1.w = ACCJ(mi, h, 7) + bb1.w;
            float4* p = (float4*)(g_srcproj + (size_t)ng * 128 + Lb);
            p[0] = o0; p[1] = o1;
        }
    }

#pragma unroll
    for (int i = 0; i < 32; i++) acc[i] = 0.f;
    gemm512(sAB, sWD, rg, cg, lq, lm, acc);
#pragma unroll
    for (int mi = 0; mi < 2; mi++)
#pragma unroll
    for (int h = 0; h < 2; h++) {
        const int ng = base + 32 * rg + 16 * mi + 8 * h + lq;
        if (ng < N_NODES) {
            float4 o0, o1;
            o0.x = ACCJ(mi, h, 0);  o0.y = ACCJ(mi, h, 1);
            o0.z = ACCJ(mi, h, 2);  o0.w = ACCJ(mi, h, 3);
            o1.x = ACCJ(mi, h, 4);  o1.y = ACCJ(mi, h, 5);
            o1.z = ACCJ(mi, h, 6);  o1.w = ACCJ(mi, h, 7);
            float4* p = (float4*)(g_dstproj + (size_t)ng * 128 + Lb);
            p[0] = o0; p[1] = o1;
        }
    }
}

// ---------------- fused edge kernel (persistent, 512 thr) ----------------
// SMEM: We[0,64K) Wo[64K,128K) A[128K,192K) LN[196608,+4K)
//       bo@200704 gamma@201216 beta@201728
#define EDGE_SMEM 202240

// Prefetch one 128x128 fp32 tile of efeat into swizzled SMEM via cp.async.
DEVINL void prefetch_efeat(uint32_t sAB, const float* __restrict__ efeat,
                           int tile, int tid) {
    const int base = tile * 128;
#pragma unroll
    for (int i = 0; i < 8; i++) {
        const int f4 = tid + 512 * i;
        const int row = f4 >> 5, c4 = f4 & 31;
        const int e = base + row;
        const bool v = e < N_EDGES;
        const float* g = efeat + (size_t)(v ? e : 0) * 128 + c4 * 4;
        cpasync16(swadr(sAB, row, c4 * 4), g, v ? 16 : 0);
    }
    cpcommit();
}

__global__ void __launch_bounds__(512, 1)
edge_kernel(const float* __restrict__ efeat, const int* __restrict__ src,
            const int* __restrict__ dst, const float* __restrict__ We,
            const float* __restrict__ Wo, const float* __restrict__ bo,
            const float* __restrict__ gamma, const float* __restrict__ beta,
            float* __restrict__ out) {
    extern __shared__ char smem[];
    const uint32_t sb = smem_u32(smem);
    const uint32_t sWE = sb, sWO = sb + 65536, sAB = sb + 131072;
    const uint32_t sLN = sb + 196608, sBO = sb + 200704, sGA = sb + 201216, sBE = sb + 201728;
    const int tid = threadIdx.x, w = tid >> 5, lane = tid & 31;
    const int lq = lane >> 2, lm = lane & 3, rg = w >> 2, cg = w & 3;

    load_weight(sWE, We, tid);
    load_weight(sWO, Wo, tid);
    if (tid < 128) {
        ((float*)(smem + 200704))[tid] = __ldg(bo + tid);
        ((float*)(smem + 201216))[tid] = __ldg(gamma + tid);
        ((float*)(smem + 201728))[tid] = __ldg(beta + tid);
    }
    // prologue: prefetch first tile (raw fp32; tf32 mma truncates low bits)
    prefetch_efeat(sAB, efeat, blockIdx.x, tid);
    __syncthreads();

    const int Lb = 32 * cg + 8 * lm;                 // thread's logical col base
    const float4 bo0 = lds128f(sBO + (uint32_t)Lb * 4);
    const float4 bo1 = lds128f(sBO + (uint32_t)Lb * 4 + 16);
    const float4 ga0 = lds128f(sGA + (uint32_t)Lb * 4);
    const float4 ga1 = lds128f(sGA + (uint32_t)Lb * 4 + 16);
    const float4 be0 = lds128f(sBE + (uint32_t)Lb * 4);
    const float4 be1 = lds128f(sBE + (uint32_t)Lb * 4 + 16);

    for (int tile = blockIdx.x; tile < ETILES; tile += GRID_E) {
        const int base = tile * 128;
        cpwait0();
        __syncthreads();                      // (a) efeat tile ready in A

        // prefetch gather indices early (consumed after GEMM1)
        int si[4], di[4];
        bool vr[4];
#pragma unroll
        for (int mi = 0; mi < 2; mi++)
#pragma unroll
        for (int h = 0; h < 2; h++) {
            const int e = base + 32 * rg + 16 * mi + 8 * h + lq;
            const bool v = e < N_EDGES;
            vr[mi * 2 + h] = v;
            si[mi * 2 + h] = v ? __ldg(src + e) : 0;
            di[mi * 2 + h] = v ? __ldg(dst + e) : 0;
        }

        float acc[32];
#pragma unroll
        for (int i = 0; i < 32; i++) acc[i] = 0.f;
        gemm512(sAB, sWE, rg, cg, lq, lm, acc);   // h-pre = efeat @ We^T
        __syncthreads();                      // (c) all warps done reading A

        // epilogue1: + srcproj[src] (b1 folded) + dstproj[dst], SiLU, act -> A
#pragma unroll
        for (int mi = 0; mi < 2; mi++)
#pragma unroll
        for (int h = 0; h < 2; h++) {
            const int R = 32 * rg + 16 * mi + 8 * h + lq;
            const float4* ps = (const float4*)(g_srcproj + (size_t)si[mi * 2 + h] * 128 + Lb);
            const float4* pd = (const float4*)(g_dstproj + (size_t)di[mi * 2 + h] * 128 + Lb);
            float4 s0 = __ldg(ps), s1 = __ldg(ps + 1);
            float4 d0 = __ldg(pd), d1 = __ldg(pd + 1);
            float x0 = silu_f(ACCJ(mi, h, 0) + s0.x + d0.x);
            float x1 = silu_f(ACCJ(mi, h, 1) + s0.y + d0.y);
            float x2 = silu_f(ACCJ(mi, h, 2) + s0.z + d0.z);
            float x3 = silu_f(ACCJ(mi, h, 3) + s0.w + d0.w);
            float x4 = silu_f(ACCJ(mi, h, 4) + s1.x + d1.x);
            float x5 = silu_f(ACCJ(mi, h, 5) + s1.y + d1.y);
            float x6 = silu_f(ACCJ(mi, h, 6) + s1.z + d1.z);
            float x7 = silu_f(ACCJ(mi, h, 7) + s1.w + d1.w);
            sts128(swadr(sAB, R, Lb),     tf32c(x0), tf32c(x1), tf32c(x2), tf32c(x3));
            sts128(swadr(sAB, R, Lb + 4), tf32c(x4), tf32c(x5), tf32c(x6), tf32c(x7));
        }
        __syncthreads();                      // (d) act tile complete

#pragma unroll
        for (int i = 0; i < 32; i++) acc[i] = 0.f;
        gemm512(sAB, sWO, rg, cg, lq, lm, acc);   // o-pre = act @ Wo^T

        // epilogue2a: + bo, LayerNorm partials (quad shfl + cross-warp SMEM)
#pragma unroll
        for (int mi = 0; mi < 2; mi++)
#pragma unroll
        for (int h = 0; h < 2; h++) {
            float s = 0.f, q = 0.f;
#pragma unroll
            for (int j = 0; j < 8; j++) {
                const float b = (j < 4) ? ((const float*)&bo0)[j] : ((const float*)&bo1)[j - 4];
                float x = ACCJ(mi, h, j) + b;
                ACCJ(mi, h, j) = x;
                s += x;
                q += x * x;
            }
            s += __shfl_xor_sync(0xffffffffu, s, 1);
            q += __shfl_xor_sync(0xffffffffu, q, 1);
            s += __shfl_xor_sync(0xffffffffu, s, 2);
            q += __shfl_xor_sync(0xffffffffu, q, 2);
            if (lm == 0) {
                const int R = 32 * rg + 16 * mi + 8 * h + lq;
                sts64f(sLN + (uint32_t)(cg * 128 + R) * 8, s, q);
            }
        }
        __syncthreads();                      // (e) LN partials visible; A free

        // prefetch next tile's efeat into A (overlaps epilogue2b)
        if (tile + GRID_E < ETILES)
            prefetch_efeat(sAB, efeat, tile + GRID_E, tid);

        // epilogue2b: normalize, affine, + residual efeat (L2-hot), store
#pragma unroll
        for (int mi = 0; mi < 2; mi++)
#pragma unroll
        for (int h = 0; h < 2; h++) {
            const int R = 32 * rg + 16 * mi + 8 * h + lq;
            const int e = base + R;
            const bool v = vr[mi * 2 + h];
            float2 p0 = *(float2*)(smem + (sLN - sb) + (uint32_t)R * 8);
            float2 p1 = *(float2*)(smem + (sLN - sb) + (uint32_t)(128 + R) * 8);
            float2 p2 = *(float2*)(smem + (sLN - sb) + (uint32_t)(256 + R) * 8);
            float2 p3 = *(float2*)(smem + (sLN - sb) + (uint32_t)(384 + R) * 8);
            const float mu  = (p0.x + p1.x + p2.x + p3.x) * 0.0078125f;
            const float var = (p0.y + p1.y + p2.y + p3.y) * 0.0078125f - mu * mu;
            const float rs  = rsqrtf(var + 1e-5f);
            const float4* pe = (const float4*)(efeat + (size_t)(v ? e : 0) * 128 + Lb);
            float4 r0 = v ? __ldg(pe)     : make_float4(0.f, 0.f, 0.f, 0.f);
            float4 r1 = v ? __ldg(pe + 1) : make_float4(0.f, 0.f, 0.f, 0.f);
            float4 o0, o1;
            o0.x = (ACCJ(mi, h, 0) - mu) * rs * ga0.x + be0.x + r0.x;
            o0.y = (ACCJ(mi, h, 1) - mu) * rs * ga0.y + be0.y + r0.y;
            o0.z = (ACCJ(mi, h, 2) - mu) * rs * ga0.z + be0.z + r0.z;
            o0.w = (ACCJ(mi, h, 3) - mu) * rs * ga0.w + be0.w + r0.w;
            o1.x = (ACCJ(mi, h, 4) - mu) * rs * ga1.x + be1.x + r1.x;
            o1.y = (ACCJ(mi, h, 5) - mu) * rs * ga1.y + be1.y + r1.y;
            o1.z = (ACCJ(mi, h, 6) - mu) * rs * ga1.z + be1.z + r1.z;
            o1.w = (ACCJ(mi, h, 7) - mu) * rs * ga1.w + be1.w + r1.w;
            if (v) {
                float4* po = (float4*)(out + (size_t)e * 128 + Lb);
                po[0] = o0; po[1] = o1;
            }
        }
    }
}

// ---------------- launch ----------------

extern "C" void kernel_launch(void* const* d_in, const int* in_sizes, int n_in,
                              void* d_out, int out_size) {
    const float* efeat = (const float*)d_in[0];
    const float* nfeat = (const float*)d_in[1];
    const int*   src   = (const int*)d_in[2];
    const int*   dst   = (const int*)d_in[3];
    const float* We    = (const float*)d_in[4];
    const float* Ws    = (const float*)d_in[5];
    const float* Wd    = (const float*)d_in[6];
    const float* b1    = (const float*)d_in[7];
    const float* Wo    = (const float*)d_in[8];
    const float* bo    = (const float*)d_in[9];
    const float* gamma = (const float*)d_in[10];
    const float* beta  = (const float*)d_in[11];
    float* out = (float*)d_out;

    cudaFuncSetAttribute(node_kernel, cudaFuncAttributeMaxDynamicSharedMemorySize, NODE_SMEM);
    cudaFuncSetAttribute(edge_kernel, cudaFuncAttributeMaxDynamicSharedMemorySize, EDGE_SMEM);

    // node kernel also writes the nfeat passthrough output
    node_kernel<<<NTILES, 512, NODE_SMEM>>>(nfeat, Ws, Wd, b1,
                                            out + (size_t)N_EDGES * 128);
    edge_kernel<<<GRID_E, 512, EDGE_SMEM>>>(efeat, src, dst, We, Wo, bo, gamma, beta, out);
}